// round 6
// baseline (speedup 1.0000x reference)
#include <cuda_runtime.h>
#include <cstdint>
#include <cstddef>

#define R_  8
#define K_  32
#define B_  1024
#define D_  256
#define L_  16
#define RK_ (R_ * K_)
#define BT_ 128

// Scratch: per-(r,k,b) assignment loss (1 MB) + stat partials + arrival ctr.
__device__ float g_loss[RK_ * B_];
__device__ float g_cnt[RK_];
__device__ float g_vsum[RK_];
__device__ float g_osum[R_];
__device__ unsigned int g_arrive;   // zero-init at load; reset by last user

// ---------------- packed f32x2 helpers (Blackwell FFMA2 path) ----------------

__device__ __forceinline__ unsigned long long pack2(float lo, float hi) {
    unsigned long long r;
    asm("mov.b64 %0, {%1, %2};" : "=l"(r)
        : "r"(__float_as_uint(lo)), "r"(__float_as_uint(hi)));
    return r;
}
__device__ __forceinline__ void unpack2(unsigned long long p, float& lo, float& hi) {
    unsigned int a, b;
    asm("mov.b64 {%0, %1}, %2;" : "=r"(a), "=r"(b) : "l"(p));
    lo = __uint_as_float(a);
    hi = __uint_as_float(b);
}
__device__ __forceinline__ unsigned long long ffma2(unsigned long long a,
                                                    unsigned long long b,
                                                    unsigned long long c) {
    unsigned long long d;
    asm("fma.rn.f32x2 %0, %1, %2, %3;" : "=l"(d) : "l"(a), "l"(b), "l"(c));
    return d;
}
__device__ __forceinline__ unsigned long long fadd2(unsigned long long a,
                                                    unsigned long long b) {
    unsigned long long d;
    asm("add.rn.f32x2 %0, %1, %2;" : "=l"(d) : "l"(a), "l"(b));
    return d;
}

// ---------------------------------------------------------------------------
// Kernel 1: fused x_ = z @ Us^T and loss[b] = 0.5 * sum_d (x[b,d]-x_[b,d])^2
// grid = (B/BT, RK), block = 256 threads.
// Thread t owns d-quad dq = (t & 63) and b-group (t >> 6) of 32 b's.
// z is staged DUPLICATED in smem ({v,v} float2 pairs) so the f32x2 multiplier
// comes straight out of a uniform LDS.128 broadcast — zero pack MOVs in the
// main loop. Us quad lives in registers as packed (d0,d1)/(d2,d3) pairs.
// ---------------------------------------------------------------------------
__global__ __launch_bounds__(256, 2) void ksub_gemm_loss(
    const float* __restrict__ x,      // (B, D)
    const float* __restrict__ z,      // (R, K, B, L)
    const float* __restrict__ Us,     // (R, K, D, L)
    float* __restrict__ x_out)        // (R, K, B, D)
{
    const int tid = threadIdx.x;
    const int dq  = tid & 63;         // d-quad index, d = 4*dq
    const int bg  = tid >> 6;         // 0..3 b-group
    const int rk  = blockIdx.y;
    const int b0  = blockIdx.x * BT_;

    // Zero the stat partials once per launch (any single block, before assign)
    if (blockIdx.x == 0 && blockIdx.y == 0) {
        if (tid < RK_) { g_cnt[tid] = 0.f; g_vsum[tid] = 0.f; }
        if (tid < R_)  g_osum[tid] = 0.f;
    }

    // z tile duplicated: zd[b*16 + l] = {z, z}. 128*16*8B = 16 KB.
    __shared__ __align__(16) float2 zd[BT_ * L_];
    // per-(b, dq) loss partials; pad 68 -> row 272B (16B-aligned)
    __shared__ __align__(16) float arr[BT_][68];

    // ---- Load Us quad, pack into f32x2 pairs: p01 = (d0,d1), p23 = (d2,d3)
    unsigned long long p01[L_], p23[L_];
    {
        const float4* u4 =
            reinterpret_cast<const float4*>(Us + ((size_t)rk * D_ + dq * 4) * L_);
        float4 A0 = u4[0],  A1 = u4[1],  A2 = u4[2],  A3 = u4[3];    // row d0
        float4 B0 = u4[4],  B1 = u4[5],  B2 = u4[6],  B3 = u4[7];    // row d1
        float4 C0 = u4[8],  C1 = u4[9],  C2 = u4[10], C3 = u4[11];   // row d2
        float4 E0 = u4[12], E1 = u4[13], E2 = u4[14], E3 = u4[15];   // row d3
        p01[0]  = pack2(A0.x, B0.x); p01[1]  = pack2(A0.y, B0.y);
        p01[2]  = pack2(A0.z, B0.z); p01[3]  = pack2(A0.w, B0.w);
        p01[4]  = pack2(A1.x, B1.x); p01[5]  = pack2(A1.y, B1.y);
        p01[6]  = pack2(A1.z, B1.z); p01[7]  = pack2(A1.w, B1.w);
        p01[8]  = pack2(A2.x, B2.x); p01[9]  = pack2(A2.y, B2.y);
        p01[10] = pack2(A2.z, B2.z); p01[11] = pack2(A2.w, B2.w);
        p01[12] = pack2(A3.x, B3.x); p01[13] = pack2(A3.y, B3.y);
        p01[14] = pack2(A3.z, B3.z); p01[15] = pack2(A3.w, B3.w);
        p23[0]  = pack2(C0.x, E0.x); p23[1]  = pack2(C0.y, E0.y);
        p23[2]  = pack2(C0.z, E0.z); p23[3]  = pack2(C0.w, E0.w);
        p23[4]  = pack2(C1.x, E1.x); p23[5]  = pack2(C1.y, E1.y);
        p23[6]  = pack2(C1.z, E1.z); p23[7]  = pack2(C1.w, E1.w);
        p23[8]  = pack2(C2.x, E2.x); p23[9]  = pack2(C2.y, E2.y);
        p23[10] = pack2(C2.z, E2.z); p23[11] = pack2(C2.w, E2.w);
        p23[12] = pack2(C3.x, E3.x); p23[13] = pack2(C3.y, E3.y);
        p23[14] = pack2(C3.z, E3.z); p23[15] = pack2(C3.w, E3.w);
    }

    // ---- Stage z tile, DUPLICATED ({v,v} per element)
    {
        const float4* zg =
            reinterpret_cast<const float4*>(z + ((size_t)rk * B_ + b0) * L_);
        float4* zd4 = reinterpret_cast<float4*>(zd);
        const float4 a  = zg[tid];
        const float4 c4 = zg[tid + 256];
        zd4[tid * 2 + 0]   = make_float4(a.x, a.x, a.y, a.y);
        zd4[tid * 2 + 1]   = make_float4(a.z, a.z, a.w, a.w);
        zd4[tid * 2 + 512] = make_float4(c4.x, c4.x, c4.y, c4.y);
        zd4[tid * 2 + 513] = make_float4(c4.z, c4.z, c4.w, c4.w);
    }
    __syncthreads();

    const float4* x4 =
        reinterpret_cast<const float4*>(x) + (size_t)b0 * (D_ / 4) + dq;
    float4* o4 =
        reinterpret_cast<float4*>(x_out) +
        ((size_t)rk * B_ + b0) * (D_ / 4) + dq;

    const ulonglong2* zr = reinterpret_cast<const ulonglong2*>(zd);

    const int blo = bg * 32;
    #pragma unroll 2
    for (int b = blo; b < blo + 32; ++b) {
        // 4 independent FFMA2 chains (dep gap 8 >= lat 4)
        unsigned long long a01a = 0ull, a01b = 0ull;
        unsigned long long a23a = 0ull, a23b = 0ull;
        #pragma unroll
        for (int l4 = 0; l4 < 4; ++l4) {
            // uniform broadcast LDS.128: two duplicated z values each
            const ulonglong2 q0 = zr[b * 8 + l4 * 2];
            const ulonglong2 q1 = zr[b * 8 + l4 * 2 + 1];
            a01a = ffma2(q0.x, p01[l4 * 4 + 0], a01a);
            a23a = ffma2(q0.x, p23[l4 * 4 + 0], a23a);
            a01b = ffma2(q0.y, p01[l4 * 4 + 1], a01b);
            a23b = ffma2(q0.y, p23[l4 * 4 + 1], a23b);
            a01a = ffma2(q1.x, p01[l4 * 4 + 2], a01a);
            a23a = ffma2(q1.x, p23[l4 * 4 + 2], a23a);
            a01b = ffma2(q1.y, p01[l4 * 4 + 3], a01b);
            a23b = ffma2(q1.y, p23[l4 * 4 + 3], a23b);
        }
        const unsigned long long acc01 = fadd2(a01a, a01b);
        const unsigned long long acc23 = fadd2(a23a, a23b);

        float v0, v1, v2, v3;
        unpack2(acc01, v0, v1);
        unpack2(acc23, v2, v3);

        o4[(size_t)b * (D_ / 4)] = make_float4(v0, v1, v2, v3);  // coalesced 512B

        const float4 xv = __ldg(x4 + (size_t)b * (D_ / 4));
        const float d0 = xv.x - v0, d1 = xv.y - v1;
        const float d2 = xv.z - v2, d3 = xv.w - v3;
        arr[b][dq] = fmaf(d3, d3, fmaf(d2, d2, fmaf(d1, d1, d0 * d0)));
    }
    __syncthreads();

    // ---- Deferred loss reduction: thread t < 128 sums arr[t][0..63].
    if (tid < BT_) {
        const float4* row = reinterpret_cast<const float4*>(arr[tid]);
        float4 s0 = row[0];
        #pragma unroll
        for (int j = 1; j < 16; ++j) {
            const float4 v = row[j];
            s0.x += v.x; s0.y += v.y; s0.z += v.z; s0.w += v.w;
        }
        g_loss[rk * B_ + b0 + tid] = 0.5f * ((s0.x + s0.y) + (s0.z + s0.w));
    }
}

// ---------------------------------------------------------------------------
// Kernel 2: per (b, r) top-2 (min) over K, one-hot c, partial stats.
// grid = 64 blocks: r = bx >> 3, b-tile = bx & 7. 128 threads, thread = b.
// The LAST block to finish also runs the finalize (EMAs, obj, obj_mean).
// ---------------------------------------------------------------------------
__global__ __launch_bounds__(128) void ksub_assign(
    const float* __restrict__ c_mean_in,   // (R, K)
    const float* __restrict__ value_in,    // (R, K)
    float* __restrict__ c_out,             // (B, R, K)
    float* __restrict__ obj_out,           // (R,)
    float* __restrict__ obj_mean,          // (1,)
    float* __restrict__ new_c_mean,        // (R, K)
    float* __restrict__ new_value)         // (R, K)
{
    const int r = blockIdx.x >> 3;
    const int b = (blockIdx.x & 7) * 128 + threadIdx.x;
    const int t = threadIdx.x;

    __shared__ float cnt[K_];
    __shared__ float vsum[K_];
    __shared__ float osum;
    __shared__ int is_last;
    if (t < K_) { cnt[t] = 0.f; vsum[t] = 0.f; }
    if (t == 0) osum = 0.f;
    __syncthreads();

    float m1 = 3.402823466e38f, m2 = 3.402823466e38f;
    int g = 0;
    #pragma unroll
    for (int k = 0; k < K_; k++) {
        const float l = g_loss[(r * K_ + k) * B_ + b];  // coalesced per k
        if (l < m1) { m2 = m1; m1 = l; g = k; }         // strict <: ties -> lowest idx
        else if (l < m2) { m2 = l; }
    }

    // one-hot row c[b, r, :]
    float* crow = c_out + ((size_t)b * R_ + r) * K_;
    const float4 z4 = make_float4(0.f, 0.f, 0.f, 0.f);
    #pragma unroll
    for (int q = 0; q < K_ / 4; q++)
        reinterpret_cast<float4*>(crow)[q] = z4;
    crow[g] = 1.0f;

    atomicAdd(&cnt[g], 1.0f);
    atomicAdd(&vsum[g], m2 - m1);
    atomicAdd(&osum, m1);
    __syncthreads();

    if (t < K_) {
        atomicAdd(&g_cnt[r * K_ + t], cnt[t]);
        atomicAdd(&g_vsum[r * K_ + t], vsum[t]);
    }
    if (t == 0) atomicAdd(&g_osum[r], osum);

    // ---- last-block finalize
    if (t == 0) {
        __threadfence();
        is_last = (atomicAdd(&g_arrive, 1u) == 63u);
    }
    __syncthreads();
    if (!is_last) return;
    __threadfence();

    const float invB = 1.0f / (float)B_;
    #pragma unroll
    for (int i = t; i < RK_; i += 128) {
        new_c_mean[i] = 0.9f * c_mean_in[i] + 0.1f * (__ldcg(&g_cnt[i])  * invB);
        new_value [i] = 0.9f * value_in [i] + 0.1f * (__ldcg(&g_vsum[i]) * invB);
    }
    if (t < R_) obj_out[t] = __ldcg(&g_osum[t]) * invB;
    if (t == 0) {
        float s = 0.f;
        #pragma unroll
        for (int rr = 0; rr < R_; rr++) s += __ldcg(&g_osum[rr]) * invB;
        *obj_mean = s * (1.0f / (float)R_);
        g_arrive = 0;   // reset for next launch/replay
    }
}

// ---------------------------------------------------------------------------
extern "C" void kernel_launch(void* const* d_in, const int* in_sizes, int n_in,
                              void* d_out, int out_size)
{
    (void)in_sizes; (void)n_in; (void)out_size;
    const float* x   = (const float*)d_in[0];   // (B, D)
    const float* z   = (const float*)d_in[1];   // (R, K, B, L)
    const float* Us  = (const float*)d_in[2];   // (R, K, D, L)
    const float* cm  = (const float*)d_in[3];   // (R, K)
    const float* val = (const float*)d_in[4];   // (R, K)

    float* out      = (float*)d_out;
    float* x_out    = out;                                   // 67108864
    float* c_out    = x_out + (size_t)RK_ * B_ * D_;         //   262144
    float* obj_out  = c_out + (size_t)B_ * R_ * K_;          //        8
    float* obj_mean = obj_out + R_;                          //        1
    float* ncm      = obj_mean + 1;                          //      256
    float* nval     = ncm + RK_;                             //      256

    dim3 g1(B_ / BT_, RK_);
    ksub_gemm_loss<<<g1, 256>>>(x, z, Us, x_out);
    ksub_assign<<<64, 128>>>(cm, val, c_out, obj_out, obj_mean, ncm, nval);
}

// round 7
// speedup vs baseline: 1.0420x; 1.0420x over previous
#include <cuda_runtime.h>
#include <cstdint>
#include <cstddef>

#define R_  8
#define K_  32
#define B_  1024
#define D_  256
#define L_  16
#define RK_ (R_ * K_)
#define BT_ 128

// Scratch: per-(r,k,b) assignment loss (1 MB) + stat partials + arrival ctr.
__device__ float g_loss[RK_ * B_];
__device__ float g_cnt[RK_];
__device__ float g_vsum[RK_];
__device__ float g_osum[R_];
__device__ unsigned int g_arrive;   // zero-init at load; reset by last user

// ---------------- packed f32x2 helpers (Blackwell FFMA2 path) ----------------

__device__ __forceinline__ void unpack2(unsigned long long p, float& lo, float& hi) {
    unsigned int a, b;
    asm("mov.b64 {%0, %1}, %2;" : "=r"(a), "=r"(b) : "l"(p));
    lo = __uint_as_float(a);
    hi = __uint_as_float(b);
}
__device__ __forceinline__ unsigned long long ffma2(unsigned long long a,
                                                    unsigned long long b,
                                                    unsigned long long c) {
    unsigned long long d;
    asm("fma.rn.f32x2 %0, %1, %2, %3;" : "=l"(d) : "l"(a), "l"(b), "l"(c));
    return d;
}
__device__ __forceinline__ unsigned long long fadd2(unsigned long long a,
                                                    unsigned long long b) {
    unsigned long long d;
    asm("add.rn.f32x2 %0, %1, %2;" : "=l"(d) : "l"(a), "l"(b));
    return d;
}

// ---------------------------------------------------------------------------
// Kernel 1: fused x_ = z @ Us^T and loss[b] = 0.5 * sum_d (x[b,d]-x_[b,d])^2
// grid = (B/BT, RK), block = 256 threads.
// Thread t owns d-quad dq = (t & 63) (d = 4*dq..4*dq+3) and b-group (t >> 6).
// K-SPLIT packing: both FFMA2 operands use the natural (l, l+1) pair layout —
//   acc_d += {z_l, z_{l+1}} * {u_{d,l}, u_{d,l+1}}
// so z comes straight from 4 uniform LDS.128 per b and Us is loaded directly
// as ulonglong2 from global. ZERO pack/dup instructions in the whole kernel.
// ---------------------------------------------------------------------------
__global__ __launch_bounds__(256, 2) void ksub_gemm_loss(
    const float* __restrict__ x,      // (B, D)
    const float* __restrict__ z,      // (R, K, B, L)
    const float* __restrict__ Us,     // (R, K, D, L)
    float* __restrict__ x_out)        // (R, K, B, D)
{
    const int tid = threadIdx.x;
    const int dq  = tid & 63;         // d-quad index, d = 4*dq
    const int bg  = tid >> 6;         // 0..3 b-group
    const int rk  = blockIdx.y;
    const int b0  = blockIdx.x * BT_;

    // Zero the stat partials once per launch (runs before ksub_assign).
    if (blockIdx.x == 0 && blockIdx.y == 0) {
        if (tid < RK_) { g_cnt[tid] = 0.f; g_vsum[tid] = 0.f; }
        if (tid < R_)  g_osum[tid] = 0.f;
    }

    // z tile, natural layout: 128 * 16 floats = 8 KB.
    __shared__ __align__(16) float4 zs4[BT_ * 4];
    // per-(b, dq) loss partials; pad 68 -> row 272B (16B-aligned)
    __shared__ __align__(16) float arr[BT_][68];

    // ---- Us quad in natural packed pairs: u[d][j] = {u_{d,2j}, u_{d,2j+1}}
    unsigned long long u[4][8];
    {
        const ulonglong2* ug =
            reinterpret_cast<const ulonglong2*>(Us + ((size_t)rk * D_ + dq * 4) * L_);
        #pragma unroll
        for (int d = 0; d < 4; ++d) {
            #pragma unroll
            for (int q = 0; q < 4; ++q) {
                const ulonglong2 v = ug[d * 4 + q];
                u[d][q * 2 + 0] = v.x;
                u[d][q * 2 + 1] = v.y;
            }
        }
    }

    // ---- Stage z tile (contiguous copy, no transpose, no duplication)
    {
        const float4* zg =
            reinterpret_cast<const float4*>(z + ((size_t)rk * B_ + b0) * L_);
        zs4[tid]       = zg[tid];
        zs4[tid + 256] = zg[tid + 256];
    }
    __syncthreads();

    const float4* x4 =
        reinterpret_cast<const float4*>(x) + (size_t)b0 * (D_ / 4) + dq;
    float4* o4 =
        reinterpret_cast<float4*>(x_out) +
        ((size_t)rk * B_ + b0) * (D_ / 4) + dq;

    const ulonglong2* zr = reinterpret_cast<const ulonglong2*>(zs4);

    const int blo = bg * 32;
    #pragma unroll 2
    for (int b = blo; b < blo + 32; ++b) {
        // 8 natural z pairs via 4 uniform broadcast LDS.128
        const ulonglong2 q0 = zr[b * 4 + 0];
        const ulonglong2 q1 = zr[b * 4 + 1];
        const ulonglong2 q2 = zr[b * 4 + 2];
        const ulonglong2 q3 = zr[b * 4 + 3];

        // 8 independent chains (accA/accB per d), dep distance 8 >= lat 4
        unsigned long long accA0 = 0ull, accB0 = 0ull;
        unsigned long long accA1 = 0ull, accB1 = 0ull;
        unsigned long long accA2 = 0ull, accB2 = 0ull;
        unsigned long long accA3 = 0ull, accB3 = 0ull;

        accA0 = ffma2(q0.x, u[0][0], accA0);
        accA1 = ffma2(q0.x, u[1][0], accA1);
        accA2 = ffma2(q0.x, u[2][0], accA2);
        accA3 = ffma2(q0.x, u[3][0], accA3);
        accB0 = ffma2(q0.y, u[0][1], accB0);
        accB1 = ffma2(q0.y, u[1][1], accB1);
        accB2 = ffma2(q0.y, u[2][1], accB2);
        accB3 = ffma2(q0.y, u[3][1], accB3);

        accA0 = ffma2(q1.x, u[0][2], accA0);
        accA1 = ffma2(q1.x, u[1][2], accA1);
        accA2 = ffma2(q1.x, u[2][2], accA2);
        accA3 = ffma2(q1.x, u[3][2], accA3);
        accB0 = ffma2(q1.y, u[0][3], accB0);
        accB1 = ffma2(q1.y, u[1][3], accB1);
        accB2 = ffma2(q1.y, u[2][3], accB2);
        accB3 = ffma2(q1.y, u[3][3], accB3);

        accA0 = ffma2(q2.x, u[0][4], accA0);
        accA1 = ffma2(q2.x, u[1][4], accA1);
        accA2 = ffma2(q2.x, u[2][4], accA2);
        accA3 = ffma2(q2.x, u[3][4], accA3);
        accB0 = ffma2(q2.y, u[0][5], accB0);
        accB1 = ffma2(q2.y, u[1][5], accB1);
        accB2 = ffma2(q2.y, u[2][5], accB2);
        accB3 = ffma2(q2.y, u[3][5], accB3);

        accA0 = ffma2(q3.x, u[0][6], accA0);
        accA1 = ffma2(q3.x, u[1][6], accA1);
        accA2 = ffma2(q3.x, u[2][6], accA2);
        accA3 = ffma2(q3.x, u[3][6], accA3);
        accB0 = ffma2(q3.y, u[0][7], accB0);
        accB1 = ffma2(q3.y, u[1][7], accB1);
        accB2 = ffma2(q3.y, u[2][7], accB2);
        accB3 = ffma2(q3.y, u[3][7], accB3);

        const unsigned long long s0 = fadd2(accA0, accB0);
        const unsigned long long s1 = fadd2(accA1, accB1);
        const unsigned long long s2 = fadd2(accA2, accB2);
        const unsigned long long s3 = fadd2(accA3, accB3);

        float l0, h0, l1, h1, l2, h2, l3, h3;
        unpack2(s0, l0, h0);
        unpack2(s1, l1, h1);
        unpack2(s2, l2, h2);
        unpack2(s3, l3, h3);
        const float v0 = l0 + h0, v1 = l1 + h1;
        const float v2 = l2 + h2, v3 = l3 + h3;

        // streaming store: x_ is write-once, keep x / g_loss resident in L2
        __stcs(o4 + (size_t)b * (D_ / 4), make_float4(v0, v1, v2, v3));

        const float4 xv = __ldg(x4 + (size_t)b * (D_ / 4));
        const float d0 = xv.x - v0, d1 = xv.y - v1;
        const float d2 = xv.z - v2, d3 = xv.w - v3;
        arr[b][dq] = fmaf(d3, d3, fmaf(d2, d2, fmaf(d1, d1, d0 * d0)));
    }
    __syncthreads();

    // ---- Deferred loss reduction: thread t < 128 sums arr[t][0..63].
    if (tid < BT_) {
        const float4* row = reinterpret_cast<const float4*>(arr[tid]);
        float4 s0 = row[0];
        #pragma unroll
        for (int j = 1; j < 16; ++j) {
            const float4 v = row[j];
            s0.x += v.x; s0.y += v.y; s0.z += v.z; s0.w += v.w;
        }
        g_loss[rk * B_ + b0 + tid] = 0.5f * ((s0.x + s0.y) + (s0.z + s0.w));
    }
}

// ---------------------------------------------------------------------------
// Kernel 2: warp per (b, r): lane = k. Shuffle top-2 (min) over K, coalesced
// one-hot row, direct global atomic stats. grid = 2048 blocks x 128 threads.
// The LAST block also runs the finalize (EMAs, obj, obj_mean).
// ---------------------------------------------------------------------------
__global__ __launch_bounds__(128) void ksub_assign(
    const float* __restrict__ c_mean_in,   // (R, K)
    const float* __restrict__ value_in,    // (R, K)
    float* __restrict__ c_out,             // (B, R, K)
    float* __restrict__ obj_out,           // (R,)
    float* __restrict__ obj_mean,          // (1,)
    float* __restrict__ new_c_mean,        // (R, K)
    float* __restrict__ new_value)         // (R, K)
{
    const int t    = threadIdx.x;
    const int lane = t & 31;
    const int widx = blockIdx.x * 4 + (t >> 5);   // 0..8191
    const int r    = widx & 7;
    const int b    = widx >> 3;

    // lane k reads loss[b, r, k]
    const float l = g_loss[(r * K_ + lane) * B_ + b];

    // argmin with lowest-index tie-break (matches jax top_k ordering)
    float mv = l; int mi = lane;
    #pragma unroll
    for (int off = 16; off >= 1; off >>= 1) {
        const float ov = __shfl_xor_sync(0xffffffffu, mv, off);
        const int   oi = __shfl_xor_sync(0xffffffffu, mi, off);
        if (ov < mv || (ov == mv && oi < mi)) { mv = ov; mi = oi; }
    }
    // second-best: exclude the winner lane, plain min
    float m2 = (lane == mi) ? 3.402823466e38f : l;
    #pragma unroll
    for (int off = 16; off >= 1; off >>= 1) {
        const float ov = __shfl_xor_sync(0xffffffffu, m2, off);
        m2 = fminf(m2, ov);
    }

    // one-hot row c[b, r, :] — 128B coalesced per warp
    c_out[((size_t)b * R_ + r) * K_ + lane] = (lane == mi) ? 1.0f : 0.0f;

    if (lane == 0) {
        atomicAdd(&g_cnt[r * K_ + mi], 1.0f);
        atomicAdd(&g_vsum[r * K_ + mi], m2 - mv);
        atomicAdd(&g_osum[r], mv);
    }

    // ---- last-block finalize
    __shared__ int is_last;
    __syncthreads();
    if (t == 0) {
        __threadfence();
        is_last = (atomicAdd(&g_arrive, 1u) == (unsigned)(gridDim.x - 1));
    }
    __syncthreads();
    if (!is_last) return;
    __threadfence();

    const float invB = 1.0f / (float)B_;
    for (int i = t; i < RK_; i += 128) {
        new_c_mean[i] = 0.9f * c_mean_in[i] + 0.1f * (__ldcg(&g_cnt[i])  * invB);
        new_value [i] = 0.9f * value_in [i] + 0.1f * (__ldcg(&g_vsum[i]) * invB);
    }
    if (t < R_) obj_out[t] = __ldcg(&g_osum[t]) * invB;
    if (t == 0) {
        float s = 0.f;
        #pragma unroll
        for (int rr = 0; rr < R_; rr++) s += __ldcg(&g_osum[rr]) * invB;
        *obj_mean = s * (1.0f / (float)R_);
        g_arrive = 0;   // reset for next replay
    }
}

// ---------------------------------------------------------------------------
extern "C" void kernel_launch(void* const* d_in, const int* in_sizes, int n_in,
                              void* d_out, int out_size)
{
    (void)in_sizes; (void)n_in; (void)out_size;
    const float* x   = (const float*)d_in[0];   // (B, D)
    const float* z   = (const float*)d_in[1];   // (R, K, B, L)
    const float* Us  = (const float*)d_in[2];   // (R, K, D, L)
    const float* cm  = (const float*)d_in[3];   // (R, K)
    const float* val = (const float*)d_in[4];   // (R, K)

    float* out      = (float*)d_out;
    float* x_out    = out;                                   // 67108864
    float* c_out    = x_out + (size_t)RK_ * B_ * D_;         //   262144
    float* obj_out  = c_out + (size_t)B_ * R_ * K_;          //        8
    float* obj_mean = obj_out + R_;                          //        1
    float* ncm      = obj_mean + 1;                          //      256
    float* nval     = ncm + RK_;                             //      256

    dim3 g1(B_ / BT_, RK_);
    ksub_gemm_loss<<<g1, 256>>>(x, z, Us, x_out);
    ksub_assign<<<2048, 128>>>(cm, val, c_out, obj_out, obj_mean, ncm, nval);
}

// round 8
// speedup vs baseline: 1.1332x; 1.0875x over previous
#include <cuda_runtime.h>
#include <cstdint>
#include <cstddef>

#define R_  8
#define K_  32
#define B_  1024
#define D_  256
#define L_  16
#define RK_ (R_ * K_)
#define BT_ 128
#define OSUM_SLOTS 32

// Scratch. g_loss is B-MAJOR: g_loss[b * RK + r*K + k]  (1 MB).
__device__ float g_loss[B_ * RK_];
__device__ float g_cnt[RK_];
__device__ float g_vsum[RK_];
__device__ float g_osum_p[R_ * OSUM_SLOTS];
__device__ unsigned int g_arrive;   // zero-init at load; reset by last user

// ---------------- packed f32x2 helpers (Blackwell FFMA2 path) ----------------

__device__ __forceinline__ void unpack2(unsigned long long p, float& lo, float& hi) {
    unsigned int a, b;
    asm("mov.b64 {%0, %1}, %2;" : "=r"(a), "=r"(b) : "l"(p));
    lo = __uint_as_float(a);
    hi = __uint_as_float(b);
}
__device__ __forceinline__ unsigned long long ffma2(unsigned long long a,
                                                    unsigned long long b,
                                                    unsigned long long c) {
    unsigned long long d;
    asm("fma.rn.f32x2 %0, %1, %2, %3;" : "=l"(d) : "l"(a), "l"(b), "l"(c));
    return d;
}
__device__ __forceinline__ unsigned long long fadd2(unsigned long long a,
                                                    unsigned long long b) {
    unsigned long long d;
    asm("add.rn.f32x2 %0, %1, %2;" : "=l"(d) : "l"(a), "l"(b));
    return d;
}

// ---------------------------------------------------------------------------
// Kernel 1: fused x_ = z @ Us^T and loss[b] = 0.5 * sum_d (x[b,d]-x_[b,d])^2
// grid = (B/BT, RK), block = 256 threads.
// Thread t owns d-quad dq = (t & 63) and b-group (t >> 6) of 32 b's.
// K-SPLIT packing: acc_d += {z_l, z_{l+1}} * {u_{d,l}, u_{d,l+1}} — both
// operands in natural (l, l+1) layout, zero pack/dup instructions.
// ---------------------------------------------------------------------------
__global__ __launch_bounds__(256, 2) void ksub_gemm_loss(
    const float* __restrict__ x,      // (B, D)
    const float* __restrict__ z,      // (R, K, B, L)
    const float* __restrict__ Us,     // (R, K, D, L)
    float* __restrict__ x_out)        // (R, K, B, D)
{
    const int tid = threadIdx.x;
    const int dq  = tid & 63;         // d-quad index, d = 4*dq
    const int bg  = tid >> 6;         // 0..3 b-group
    const int rk  = blockIdx.y;
    const int b0  = blockIdx.x * BT_;

    // Zero the stat partials once per launch (runs before ksub_assign).
    if (blockIdx.x == 0 && blockIdx.y == 0) {
        if (tid < RK_) { g_cnt[tid] = 0.f; g_vsum[tid] = 0.f; }
        if (tid < R_ * OSUM_SLOTS) g_osum_p[tid] = 0.f;
    }

    // z tile, natural layout: 128 * 16 floats = 8 KB.
    __shared__ __align__(16) float4 zs4[BT_ * 4];
    // per-(b, dq) loss partials; pad 68 -> row 272B (16B-aligned)
    __shared__ __align__(16) float arr[BT_][68];

    // ---- Us quad in natural packed pairs: u[d][j] = {u_{d,2j}, u_{d,2j+1}}
    unsigned long long u[4][8];
    {
        const ulonglong2* ug =
            reinterpret_cast<const ulonglong2*>(Us + ((size_t)rk * D_ + dq * 4) * L_);
        #pragma unroll
        for (int d = 0; d < 4; ++d) {
            #pragma unroll
            for (int q = 0; q < 4; ++q) {
                const ulonglong2 v = ug[d * 4 + q];
                u[d][q * 2 + 0] = v.x;
                u[d][q * 2 + 1] = v.y;
            }
        }
    }

    // ---- Stage z tile (contiguous copy)
    {
        const float4* zg =
            reinterpret_cast<const float4*>(z + ((size_t)rk * B_ + b0) * L_);
        zs4[tid]       = zg[tid];
        zs4[tid + 256] = zg[tid + 256];
    }
    __syncthreads();

    const float4* x4 =
        reinterpret_cast<const float4*>(x) + (size_t)b0 * (D_ / 4) + dq;
    float4* o4 =
        reinterpret_cast<float4*>(x_out) +
        ((size_t)rk * B_ + b0) * (D_ / 4) + dq;

    const ulonglong2* zr = reinterpret_cast<const ulonglong2*>(zs4);

    const int blo = bg * 32;
    #pragma unroll 2
    for (int b = blo; b < blo + 32; ++b) {
        // 8 natural z pairs via 4 uniform broadcast LDS.128
        const ulonglong2 q0 = zr[b * 4 + 0];
        const ulonglong2 q1 = zr[b * 4 + 1];
        const ulonglong2 q2 = zr[b * 4 + 2];
        const ulonglong2 q3 = zr[b * 4 + 3];

        // 8 independent chains (accA/accB per d), dep distance 8 >= lat 4
        unsigned long long accA0 = 0ull, accB0 = 0ull;
        unsigned long long accA1 = 0ull, accB1 = 0ull;
        unsigned long long accA2 = 0ull, accB2 = 0ull;
        unsigned long long accA3 = 0ull, accB3 = 0ull;

        accA0 = ffma2(q0.x, u[0][0], accA0);
        accA1 = ffma2(q0.x, u[1][0], accA1);
        accA2 = ffma2(q0.x, u[2][0], accA2);
        accA3 = ffma2(q0.x, u[3][0], accA3);
        accB0 = ffma2(q0.y, u[0][1], accB0);
        accB1 = ffma2(q0.y, u[1][1], accB1);
        accB2 = ffma2(q0.y, u[2][1], accB2);
        accB3 = ffma2(q0.y, u[3][1], accB3);

        accA0 = ffma2(q1.x, u[0][2], accA0);
        accA1 = ffma2(q1.x, u[1][2], accA1);
        accA2 = ffma2(q1.x, u[2][2], accA2);
        accA3 = ffma2(q1.x, u[3][2], accA3);
        accB0 = ffma2(q1.y, u[0][3], accB0);
        accB1 = ffma2(q1.y, u[1][3], accB1);
        accB2 = ffma2(q1.y, u[2][3], accB2);
        accB3 = ffma2(q1.y, u[3][3], accB3);

        accA0 = ffma2(q2.x, u[0][4], accA0);
        accA1 = ffma2(q2.x, u[1][4], accA1);
        accA2 = ffma2(q2.x, u[2][4], accA2);
        accA3 = ffma2(q2.x, u[3][4], accA3);
        accB0 = ffma2(q2.y, u[0][5], accB0);
        accB1 = ffma2(q2.y, u[1][5], accB1);
        accB2 = ffma2(q2.y, u[2][5], accB2);
        accB3 = ffma2(q2.y, u[3][5], accB3);

        accA0 = ffma2(q3.x, u[0][6], accA0);
        accA1 = ffma2(q3.x, u[1][6], accA1);
        accA2 = ffma2(q3.x, u[2][6], accA2);
        accA3 = ffma2(q3.x, u[3][6], accA3);
        accB0 = ffma2(q3.y, u[0][7], accB0);
        accB1 = ffma2(q3.y, u[1][7], accB1);
        accB2 = ffma2(q3.y, u[2][7], accB2);
        accB3 = ffma2(q3.y, u[3][7], accB3);

        const unsigned long long s0 = fadd2(accA0, accB0);
        const unsigned long long s1 = fadd2(accA1, accB1);
        const unsigned long long s2 = fadd2(accA2, accB2);
        const unsigned long long s3 = fadd2(accA3, accB3);

        float l0, h0, l1, h1, l2, h2, l3, h3;
        unpack2(s0, l0, h0);
        unpack2(s1, l1, h1);
        unpack2(s2, l2, h2);
        unpack2(s3, l3, h3);
        const float v0 = l0 + h0, v1 = l1 + h1;
        const float v2 = l2 + h2, v3 = l3 + h3;

        // streaming store: x_ is write-once, keep x / g_loss resident in L2
        __stcs(o4 + (size_t)b * (D_ / 4), make_float4(v0, v1, v2, v3));

        const float4 xv = __ldg(x4 + (size_t)b * (D_ / 4));
        const float d0 = xv.x - v0, d1 = xv.y - v1;
        const float d2 = xv.z - v2, d3 = xv.w - v3;
        arr[b][dq] = fmaf(d3, d3, fmaf(d2, d2, fmaf(d1, d1, d0 * d0)));
    }
    __syncthreads();

    // ---- Deferred loss reduction: thread t < 128 sums arr[t][0..63].
    // B-MAJOR store: g_loss[b * RK + rk] (scattered 4B, L2-absorbed).
    if (tid < BT_) {
        const float4* row = reinterpret_cast<const float4*>(arr[tid]);
        float4 s0 = row[0];
        #pragma unroll
        for (int j = 1; j < 16; ++j) {
            const float4 v = row[j];
            s0.x += v.x; s0.y += v.y; s0.z += v.z; s0.w += v.w;
        }
        g_loss[(size_t)(b0 + tid) * RK_ + rk] =
            0.5f * ((s0.x + s0.y) + (s0.z + s0.w));
    }
}

// ---------------------------------------------------------------------------
// Kernel 2: warp per (b, r): lane = k. COALESCED 128B loss read (b-major),
// shuffle top-2 (min), coalesced one-hot row, de-contended atomics.
// grid = 2048 blocks x 128 threads. Last block runs the finalize.
// ---------------------------------------------------------------------------
__global__ __launch_bounds__(128) void ksub_assign(
    const float* __restrict__ c_mean_in,   // (R, K)
    const float* __restrict__ value_in,    // (R, K)
    float* __restrict__ c_out,             // (B, R, K)
    float* __restrict__ obj_out,           // (R,)
    float* __restrict__ obj_mean,          // (1,)
    float* __restrict__ new_c_mean,        // (R, K)
    float* __restrict__ new_value)         // (R, K)
{
    const int t    = threadIdx.x;
    const int lane = t & 31;
    const int widx = blockIdx.x * 4 + (t >> 5);   // 0..8191
    const int r    = widx & 7;
    const int b    = widx >> 3;

    // lane k reads loss[b, r, k] — one coalesced 128B line per warp
    const float l = g_loss[(size_t)b * RK_ + r * K_ + lane];

    // argmin with lowest-index tie-break (matches jax top_k ordering)
    float mv = l; int mi = lane;
    #pragma unroll
    for (int off = 16; off >= 1; off >>= 1) {
        const float ov = __shfl_xor_sync(0xffffffffu, mv, off);
        const int   oi = __shfl_xor_sync(0xffffffffu, mi, off);
        if (ov < mv || (ov == mv && oi < mi)) { mv = ov; mi = oi; }
    }
    // second-best: exclude the winner lane, plain min
    float m2 = (lane == mi) ? 3.402823466e38f : l;
    #pragma unroll
    for (int off = 16; off >= 1; off >>= 1) {
        const float ov = __shfl_xor_sync(0xffffffffu, m2, off);
        m2 = fminf(m2, ov);
    }

    // one-hot row c[b, r, :] — 128B coalesced per warp
    c_out[((size_t)b * R_ + r) * K_ + lane] = (lane == mi) ? 1.0f : 0.0f;

    if (lane == 0) {
        atomicAdd(&g_cnt[r * K_ + mi], 1.0f);          // ~32 adds/addr
        atomicAdd(&g_vsum[r * K_ + mi], m2 - mv);      // ~32 adds/addr
        atomicAdd(&g_osum_p[r * OSUM_SLOTS + (blockIdx.x & (OSUM_SLOTS - 1))],
                  mv);                                 // ~32 adds/addr
    }

    // ---- last-block finalize
    __shared__ int is_last;
    __syncthreads();
    if (t == 0) {
        __threadfence();
        is_last = (atomicAdd(&g_arrive, 1u) == (unsigned)(gridDim.x - 1));
    }
    __syncthreads();
    if (!is_last) return;
    __threadfence();

    const float invB = 1.0f / (float)B_;
    for (int i = t; i < RK_; i += 128) {
        new_c_mean[i] = 0.9f * c_mean_in[i] + 0.1f * (__ldcg(&g_cnt[i])  * invB);
        new_value [i] = 0.9f * value_in [i] + 0.1f * (__ldcg(&g_vsum[i]) * invB);
    }
    __shared__ float obj_sh[R_];
    if (t < R_) {
        float s = 0.f;
        #pragma unroll
        for (int j = 0; j < OSUM_SLOTS; ++j)
            s += __ldcg(&g_osum_p[t * OSUM_SLOTS + j]);
        const float o = s * invB;
        obj_out[t] = o;
        obj_sh[t] = o;
    }
    __syncthreads();
    if (t == 0) {
        float s = 0.f;
        #pragma unroll
        for (int rr = 0; rr < R_; rr++) s += obj_sh[rr];
        *obj_mean = s * (1.0f / (float)R_);
        g_arrive = 0;   // reset for next replay
    }
}

// ---------------------------------------------------------------------------
extern "C" void kernel_launch(void* const* d_in, const int* in_sizes, int n_in,
                              void* d_out, int out_size)
{
    (void)in_sizes; (void)n_in; (void)out_size;
    const float* x   = (const float*)d_in[0];   // (B, D)
    const float* z   = (const float*)d_in[1];   // (R, K, B, L)
    const float* Us  = (const float*)d_in[2];   // (R, K, D, L)
    const float* cm  = (const float*)d_in[3];   // (R, K)
    const float* val = (const float*)d_in[4];   // (R, K)

    float* out      = (float*)d_out;
    float* x_out    = out;                                   // 67108864
    float* c_out    = x_out + (size_t)RK_ * B_ * D_;         //   262144
    float* obj_out  = c_out + (size_t)B_ * R_ * K_;          //        8
    float* obj_mean = obj_out + R_;                          //        1
    float* ncm      = obj_mean + 1;                          //      256
    float* nval     = ncm + RK_;                             //      256

    dim3 g1(B_ / BT_, RK_);
    ksub_gemm_loss<<<g1, 256>>>(x, z, Us, x_out);
    ksub_assign<<<2048, 128>>>(cm, val, c_out, obj_out, obj_mean, ncm, nval);
}